// round 14
// baseline (speedup 1.0000x reference)
#include <cuda_runtime.h>
#include <math.h>

#define VOCAB  32000
#define EMBED  512
#define HIDDEN 1024
#define BATCH  64
#define SEQ    512
#define NG     4096            // 4 * HIDDEN (f,i,g,o packed)
#define M_A    (SEQ * BATCH)   // 32768 rows for the input projection GEMM
#define RCTAS  128

typedef unsigned long long ull;

// ---------------- device scratch (static: allocation-guard-safe) ------------
__device__ __align__(128) float g_xprojT[(size_t)SEQ * NG * BATCH]; // [t][col][b], bias added
__device__ __align__(128) float g_wxP[EMBED * NG];                  // Wx packed [k][col]
__device__ __align__(128) float g_whC[NG * HIDDEN];                 // Wh compact [jt][k][64 cols]
__device__ __align__(128) float g_bias[NG];
__device__ __align__(128) float g_h[2][HIDDEN * BATCH];             // h double buffer [jh][b]
__device__ __align__(128) int   g_idx[M_A];
__device__ unsigned g_cnt[SEQ];     // per-step grid barrier counters

__device__ __forceinline__ float sigmoidf_(float x) { return 1.0f / (1.0f + __expf(-x)); }

// packed fp32x2 FMA (Blackwell FFMA2): d.lo += a.lo*b.lo ; d.hi += a.hi*b.hi
__device__ __forceinline__ void fma2(ull& d, ull a, ull b) {
    asm("fma.rn.f32x2 %0, %1, %2, %0;" : "+l"(d) : "l"(a), "l"(b));
}
__device__ __forceinline__ float2 unpack2(ull v) {
    float2 f; asm("mov.b64 {%0,%1}, %2;" : "=f"(f.x), "=f"(f.y) : "l"(v)); return f;
}

// ---------------- prep: pack weights, gather indices, zero state -------------
__global__ void prep_kernel(const int* __restrict__ ids,
                            const float* __restrict__ Wf, const float* __restrict__ bf,
                            const float* __restrict__ Wi, const float* __restrict__ bi,
                            const float* __restrict__ Wc, const float* __restrict__ bc,
                            const float* __restrict__ Wo, const float* __restrict__ bo) {
    int tid = blockIdx.x * blockDim.x + threadIdx.x;
    int nt  = gridDim.x * blockDim.x;

    // Wh compact: whC[((jt*1024 + k)*64) + c], c = g*16 + (jh - jt*16)
    for (int i = tid; i < NG * HIDDEN; i += nt) {
        int c = i & 63, k = (i >> 6) & 1023, jt = i >> 16;
        int g = c >> 4, jh = jt * 16 + (c & 15);
        const float* W = (g == 0) ? Wf : (g == 1) ? Wi : (g == 2) ? Wc : Wo;
        g_whC[i] = W[(EMBED + k) * HIDDEN + jh];
    }
    // Wx packed: wxP[k*4096 + col], col = g*1024 + jh
    for (int i = tid; i < EMBED * NG; i += nt) {
        int k = i >> 12, col = i & 4095;
        int g = col >> 10, jh = col & 1023;
        const float* W = (g == 0) ? Wf : (g == 1) ? Wi : (g == 2) ? Wc : Wo;
        g_wxP[i] = W[k * HIDDEN + jh];
    }
    for (int i = tid; i < NG; i += nt) {
        int g = i >> 10, jh = i & 1023;
        const float* b = (g == 0) ? bf : (g == 1) ? bi : (g == 2) ? bc : bo;
        g_bias[i] = b[jh];
    }
    for (int i = tid; i < M_A; i += nt)
        g_idx[i] = ids[(i & 63) * SEQ + (i >> 6)];   // row m = t*64+b -> ids[b*SEQ+t]
    for (int i = tid; i < HIDDEN * BATCH; i += nt)
        g_h[0][i] = 0.0f;
    for (int i = tid; i < SEQ; i += nt)
        g_cnt[i] = 0u;
}

// ---------------- phase A: xprojT = embed[ids] @ Wx + bias (FFMA2) -----------
// M=32768, N=4096, K=512. CTA tile 128x128, 256 thr, 8x8 per thread.
// Output layout transposed: [t][col][b].
__global__ void __launch_bounds__(256, 2) gemmA_kernel(const float* __restrict__ embed) {
    __shared__ __align__(16) float Ad[8][256];   // a duplicated (a,a) pairs
    __shared__ __align__(16) float Bs[8][128];
    int tid = threadIdx.x;
    int mblk = blockIdx.y, nblk = blockIdx.x;
    int m0 = mblk * 128, n0 = nblk * 128;
    int ty = tid >> 4, tx = tid & 15;

    ull acc2[8][4];
#pragma unroll
    for (int i = 0; i < 8; i++)
#pragma unroll
        for (int q = 0; q < 4; q++) acc2[i][q] = 0ULL;

    int am = tid >> 1, ak = (tid & 1) * 4;
    int arow = g_idx[m0 + am];
    const float* aptr = embed + (size_t)arow * EMBED + ak;
    int bk = tid >> 5, bn = (tid & 31) * 4;

    for (int k0 = 0; k0 < EMBED; k0 += 8) {
        float4 av = __ldg((const float4*)(aptr + k0));
        float4 bv = __ldg((const float4*)(g_wxP + (size_t)(k0 + bk) * NG + n0 + bn));
        __syncthreads();
        *(float2*)&Ad[ak + 0][2 * am] = make_float2(av.x, av.x);
        *(float2*)&Ad[ak + 1][2 * am] = make_float2(av.y, av.y);
        *(float2*)&Ad[ak + 2][2 * am] = make_float2(av.z, av.z);
        *(float2*)&Ad[ak + 3][2 * am] = make_float2(av.w, av.w);
        *(float4*)&Bs[bk][bn] = bv;
        __syncthreads();
#pragma unroll
        for (int kk = 0; kk < 8; kk++) {
            ulonglong2 a01 = *(const ulonglong2*)&Ad[kk][ty * 16 + 0];
            ulonglong2 a23 = *(const ulonglong2*)&Ad[kk][ty * 16 + 4];
            ulonglong2 a45 = *(const ulonglong2*)&Ad[kk][ty * 16 + 8];
            ulonglong2 a67 = *(const ulonglong2*)&Ad[kk][ty * 16 + 12];
            ulonglong2 b03 = *(const ulonglong2*)&Bs[kk][tx * 8];
            ulonglong2 b47 = *(const ulonglong2*)&Bs[kk][tx * 8 + 4];
#define PROW(i, av) \
            fma2(acc2[i][0], av, b03.x); fma2(acc2[i][1], av, b03.y); \
            fma2(acc2[i][2], av, b47.x); fma2(acc2[i][3], av, b47.y);
            PROW(0, a01.x) PROW(1, a01.y)
            PROW(2, a23.x) PROW(3, a23.y)
            PROW(4, a45.x) PROW(5, a45.y)
            PROW(6, a67.x) PROW(7, a67.y)
#undef PROW
        }
    }
    // epilogue: write transposed [t][col][b] with bias.
    // thread owns rows m0 + ty*8 + i  ->  t = mblk*2 + (ty>>3), b = (ty&7)*8 + i
    int tt = mblk * 2 + (ty >> 3);
    int bb = (ty & 7) * 8;
#pragma unroll
    for (int q = 0; q < 4; q++) {
#pragma unroll
        for (int l = 0; l < 2; l++) {
            int col = n0 + tx * 8 + q * 2 + l;
            float bsv = g_bias[col];
            float v[8];
#pragma unroll
            for (int i = 0; i < 8; i++) {
                float2 u = unpack2(acc2[i][q]);
                v[i] = (l ? u.y : u.x) + bsv;
            }
            float* dst = &g_xprojT[((size_t)tt * NG + col) * BATCH + bb];
            *(float4*)dst       = make_float4(v[0], v[1], v[2], v[3]);
            *(float4*)(dst + 4) = make_float4(v[4], v[5], v[6], v[7]);
        }
    }
}

// ---------------- phase B: persistent LSTM recurrence (FFMA2) ----------------
// 128 CTAs: cta = (jt<<1) | b_half. Each CTA: 32 b x 16 jh x 4 gates (64 cols).
__global__ void __launch_bounds__(256) lstm_kernel() {
    __shared__ __align__(16) float Hs[32][32];   // h chunk  [kk][b]
    __shared__ __align__(16) float Wd[32][128];  // Wh chunk, (w,w)-duplicated pairs
    __shared__ __align__(16) float Gs[64][32];   // gate preacts [cc][b]
    __shared__ __align__(16) float cs[16][32];   // cell state [u][b] (persistent)

    int tid = threadIdx.x;
    int cta = blockIdx.x;
    int b0 = (cta & 1) * 32;
    int jt = cta >> 1;                 // jh base = jt*16
    int bg = tid & 7;                  // b group of 4
    int cg = tid >> 3;                 // col group of 2

    ((float*)cs)[tid] = 0.0f;
    ((float*)cs)[tid + 256] = 0.0f;

    int h_kk = tid >> 3, h_b4 = (tid & 7) * 4;
    const float2* wsrc = (const float2*)(g_whC + ((size_t)jt << 16)); // jt*1024*64 floats

    for (int t = 0; t < SEQ; t++) {
        const float* hc = g_h[t & 1];
        float* hn = g_h[(t + 1) & 1];

        ull acc00 = 0ULL, acc01 = 0ULL, acc10 = 0ULL, acc11 = 0ULL;

        for (int k0 = 0; k0 < HIDDEN; k0 += 32) {
            float4 hv = __ldcg((const float4*)&hc[(k0 + h_kk) * BATCH + b0 + h_b4]);
            const float2* wc = wsrc + k0 * 32;   // chunk = 32 k x 32 col-pairs
            float2 w0 = __ldg(&wc[tid]);
            float2 w1 = __ldg(&wc[tid + 256]);
            float2 w2 = __ldg(&wc[tid + 512]);
            float2 w3 = __ldg(&wc[tid + 768]);
            __syncthreads();
            *(float4*)&Hs[h_kk][h_b4] = hv;
            { int i = tid;       *(float4*)&Wd[i >> 5][(i & 31) * 4] = make_float4(w0.x, w0.x, w0.y, w0.y); }
            { int i = tid + 256; *(float4*)&Wd[i >> 5][(i & 31) * 4] = make_float4(w1.x, w1.x, w1.y, w1.y); }
            { int i = tid + 512; *(float4*)&Wd[i >> 5][(i & 31) * 4] = make_float4(w2.x, w2.x, w2.y, w2.y); }
            { int i = tid + 768; *(float4*)&Wd[i >> 5][(i & 31) * 4] = make_float4(w3.x, w3.x, w3.y, w3.y); }
            __syncthreads();
#pragma unroll
            for (int kk = 0; kk < 32; kk++) {
                ulonglong2 hp = *(const ulonglong2*)&Hs[kk][bg * 4];
                ulonglong2 wp = *(const ulonglong2*)&Wd[kk][cg * 4];
                fma2(acc00, hp.x, wp.x);
                fma2(acc10, hp.y, wp.x);
                fma2(acc01, hp.x, wp.y);
                fma2(acc11, hp.y, wp.y);
            }
        }

        // stage gate preacts: recurrent acc + precomputed x-proj (+bias)
#pragma unroll
        for (int j = 0; j < 2; j++) {
            int cc = cg * 2 + j;
            int gcol = (cc >> 4) * 1024 + jt * 16 + (cc & 15);
            float4 xv = __ldcg((const float4*)&g_xprojT[((size_t)t * NG + gcol) * BATCH + b0 + bg * 4]);
            float2 u0 = unpack2(j ? acc01 : acc00);
            float2 u1 = unpack2(j ? acc11 : acc10);
            Gs[cc][bg * 4 + 0] = u0.x + xv.x;
            Gs[cc][bg * 4 + 1] = u0.y + xv.y;
            Gs[cc][bg * 4 + 2] = u1.x + xv.z;
            Gs[cc][bg * 4 + 3] = u1.y + xv.w;
        }
        __syncthreads();

        // cell/hidden update: 2 cells per thread
#pragma unroll
        for (int e = 0; e < 2; e++) {
            int cell = tid + e * 256;
            int bb = cell & 31, u = cell >> 5;
            float f  = sigmoidf_(Gs[u][bb]);
            float ii = sigmoidf_(Gs[16 + u][bb]);
            float gg = tanhf(Gs[32 + u][bb]);
            float oo = sigmoidf_(Gs[48 + u][bb]);
            float c = cs[u][bb] * f + gg * ii;
            cs[u][bb] = c;
            hn[(jt * 16 + u) * BATCH + b0 + bb] = c * oo;   // no tanh (matches ref)
        }

        // grid-wide barrier among the 128 resident CTAs
        __threadfence();
        __syncthreads();
        if (tid == 0) {
            atomicAdd(&g_cnt[t], 1u);
            volatile unsigned* p = &g_cnt[t];
            while (*p < (unsigned)RCTAS) { }
        }
        __syncthreads();
    }
}

// ---------------- phase C: logits = h_final @ Wout + bout --------------------
__global__ void __launch_bounds__(256) gemmC_kernel(const float* __restrict__ Wout,
                                                    const float* __restrict__ bout,
                                                    float* __restrict__ out) {
    __shared__ __align__(16) float As[8][64];
    __shared__ __align__(16) float Bs[8][128];
    int tid = threadIdx.x;
    int n0 = blockIdx.x * 128;
    int ty = tid >> 4, tx = tid & 15;

    float acc[4][8];
#pragma unroll
    for (int i = 0; i < 4; i++)
#pragma unroll
        for (int j = 0; j < 8; j++) acc[i][j] = 0.0f;

    int akk = tid >> 5, am = (tid & 31) * 2;
    int bkk = tid >> 5, bn = (tid & 31) * 4;

    for (int k0 = 0; k0 < HIDDEN; k0 += 8) {
        float2 av = *(const float2*)&g_h[0][(k0 + akk) * BATCH + am];
        float4 bv = *(const float4*)(Wout + (size_t)(k0 + bkk) * VOCAB + n0 + bn);
        __syncthreads();
        *(float2*)&As[akk][am] = av;
        *(float4*)&Bs[bkk][bn] = bv;
        __syncthreads();
#pragma unroll
        for (int kk = 0; kk < 8; kk++) {
            float4 a = *(float4*)&As[kk][ty * 4];
            float4 b0 = *(float4*)&Bs[kk][tx * 8];
            float4 b1 = *(float4*)&Bs[kk][tx * 8 + 4];
            float aa[4] = {a.x, a.y, a.z, a.w};
            float bb[8] = {b0.x, b0.y, b0.z, b0.w, b1.x, b1.y, b1.z, b1.w};
#pragma unroll
            for (int i = 0; i < 4; i++)
#pragma unroll
                for (int j = 0; j < 8; j++)
                    acc[i][j] = fmaf(aa[i], bb[j], acc[i][j]);
        }
    }
#pragma unroll
    for (int i = 0; i < 4; i++) {
        int row = ty * 4 + i;
        size_t base = (size_t)row * VOCAB + n0 + tx * 8;
#pragma unroll
        for (int j = 0; j < 8; j++)
            out[base + j] = acc[i][j] + bout[n0 + tx * 8 + j];
    }
}

// ---------------- launcher ---------------------------------------------------
extern "C" void kernel_launch(void* const* d_in, const int* in_sizes, int n_in,
                              void* d_out, int out_size) {
    const int*   ids   = (const int*)d_in[0];
    const float* embed = (const float*)d_in[1];
    const float* Wf    = (const float*)d_in[2];
    const float* bf    = (const float*)d_in[3];
    const float* Wi    = (const float*)d_in[4];
    const float* bi    = (const float*)d_in[5];
    const float* Wc    = (const float*)d_in[6];
    const float* bc    = (const float*)d_in[7];
    const float* Wo    = (const float*)d_in[8];
    const float* bo    = (const float*)d_in[9];
    const float* Wout  = (const float*)d_in[10];
    const float* bout  = (const float*)d_in[11];

    prep_kernel<<<1024, 256>>>(ids, Wf, bf, Wi, bi, Wc, bc, Wo, bo);
    gemmA_kernel<<<dim3(NG / 128, M_A / 128), 256>>>(embed);
    lstm_kernel<<<RCTAS, 256>>>();
    gemmC_kernel<<<VOCAB / 128, 256>>>(Wout, bout, (float*)d_out);
}

// round 15
// speedup vs baseline: 1.0020x; 1.0020x over previous
#include <cuda_runtime.h>
#include <math.h>

#define VOCAB  32000
#define EMBED  512
#define HIDDEN 1024
#define BATCH  64
#define SEQ    512
#define NG     4096            // 4 * HIDDEN (f,i,g,o packed)
#define M_A    (SEQ * BATCH)   // 32768 rows for the input projection GEMM
#define RCTAS  128

typedef unsigned long long ull;

// ---------------- device scratch (static: allocation-guard-safe) ------------
__device__ __align__(128) float g_xprojT[(size_t)SEQ * NG * BATCH]; // [t][col][b], bias added
__device__ __align__(128) float g_wxP[EMBED * NG];                  // Wx packed [k][col]
__device__ __align__(128) float g_whC[NG * HIDDEN];                 // Wh compact [jt][k][64 cols]
__device__ __align__(128) float g_bias[NG];
__device__ __align__(128) float g_h[2][HIDDEN * BATCH];             // h double buffer [jh][b]
__device__ __align__(128) int   g_idx[M_A];
__device__ unsigned g_cnt[SEQ];     // per-step grid barrier counters

__device__ __forceinline__ float sigmoidf_(float x) { return 1.0f / (1.0f + __expf(-x)); }

// packed fp32x2 FMA (Blackwell FFMA2): d.lo += a.lo*b.lo ; d.hi += a.hi*b.hi
__device__ __forceinline__ void fma2(ull& d, ull a, ull b) {
    asm("fma.rn.f32x2 %0, %1, %2, %0;" : "+l"(d) : "l"(a), "l"(b));
}
__device__ __forceinline__ float2 unpack2(ull v) {
    float2 f; asm("mov.b64 {%0,%1}, %2;" : "=f"(f.x), "=f"(f.y) : "l"(v)); return f;
}

// ---------------- prep: pack weights, gather indices, zero state -------------
__global__ void prep_kernel(const int* __restrict__ ids,
                            const float* __restrict__ Wf, const float* __restrict__ bf,
                            const float* __restrict__ Wi, const float* __restrict__ bi,
                            const float* __restrict__ Wc, const float* __restrict__ bc,
                            const float* __restrict__ Wo, const float* __restrict__ bo) {
    int tid = blockIdx.x * blockDim.x + threadIdx.x;
    int nt  = gridDim.x * blockDim.x;

    // Wh compact: whC[((jt*1024 + k)*64) + c], c = g*16 + (jh - jt*16)
    for (int i = tid; i < NG * HIDDEN; i += nt) {
        int c = i & 63, k = (i >> 6) & 1023, jt = i >> 16;
        int g = c >> 4, jh = jt * 16 + (c & 15);
        const float* W = (g == 0) ? Wf : (g == 1) ? Wi : (g == 2) ? Wc : Wo;
        g_whC[i] = W[(EMBED + k) * HIDDEN + jh];
    }
    // Wx packed: wxP[k*4096 + col], col = g*1024 + jh
    for (int i = tid; i < EMBED * NG; i += nt) {
        int k = i >> 12, col = i & 4095;
        int g = col >> 10, jh = col & 1023;
        const float* W = (g == 0) ? Wf : (g == 1) ? Wi : (g == 2) ? Wc : Wo;
        g_wxP[i] = W[k * HIDDEN + jh];
    }
    for (int i = tid; i < NG; i += nt) {
        int g = i >> 10, jh = i & 1023;
        const float* b = (g == 0) ? bf : (g == 1) ? bi : (g == 2) ? bc : bo;
        g_bias[i] = b[jh];
    }
    for (int i = tid; i < M_A; i += nt)
        g_idx[i] = ids[(i & 63) * SEQ + (i >> 6)];   // row m = t*64+b -> ids[b*SEQ+t]
    for (int i = tid; i < HIDDEN * BATCH; i += nt)
        g_h[0][i] = 0.0f;
    for (int i = tid; i < SEQ; i += nt)
        g_cnt[i] = 0u;
}

// ---------------- phase A: xprojT = embed[ids] @ Wx + bias (FFMA2) -----------
// M=32768, N=4096, K=512. CTA tile 128x128, 256 thr, 8x8 per thread.
// Output layout transposed: [t][col][b].
__global__ void __launch_bounds__(256, 2) gemmA_kernel(const float* __restrict__ embed) {
    __shared__ __align__(16) float Ad[8][256];   // a duplicated (a,a) pairs
    __shared__ __align__(16) float Bs[8][128];
    int tid = threadIdx.x;
    int mblk = blockIdx.y, nblk = blockIdx.x;
    int m0 = mblk * 128, n0 = nblk * 128;
    int ty = tid >> 4, tx = tid & 15;

    ull acc2[8][4];
#pragma unroll
    for (int i = 0; i < 8; i++)
#pragma unroll
        for (int q = 0; q < 4; q++) acc2[i][q] = 0ULL;

    int am = tid >> 1, ak = (tid & 1) * 4;
    int arow = g_idx[m0 + am];
    const float* aptr = embed + (size_t)arow * EMBED + ak;
    int bk = tid >> 5, bn = (tid & 31) * 4;

    for (int k0 = 0; k0 < EMBED; k0 += 8) {
        float4 av = __ldg((const float4*)(aptr + k0));
        float4 bv = __ldg((const float4*)(g_wxP + (size_t)(k0 + bk) * NG + n0 + bn));
        __syncthreads();
        *(float2*)&Ad[ak + 0][2 * am] = make_float2(av.x, av.x);
        *(float2*)&Ad[ak + 1][2 * am] = make_float2(av.y, av.y);
        *(float2*)&Ad[ak + 2][2 * am] = make_float2(av.z, av.z);
        *(float2*)&Ad[ak + 3][2 * am] = make_float2(av.w, av.w);
        *(float4*)&Bs[bk][bn] = bv;
        __syncthreads();
#pragma unroll
        for (int kk = 0; kk < 8; kk++) {
            ulonglong2 a01 = *(const ulonglong2*)&Ad[kk][ty * 16 + 0];
            ulonglong2 a23 = *(const ulonglong2*)&Ad[kk][ty * 16 + 4];
            ulonglong2 a45 = *(const ulonglong2*)&Ad[kk][ty * 16 + 8];
            ulonglong2 a67 = *(const ulonglong2*)&Ad[kk][ty * 16 + 12];
            ulonglong2 b03 = *(const ulonglong2*)&Bs[kk][tx * 8];
            ulonglong2 b47 = *(const ulonglong2*)&Bs[kk][tx * 8 + 4];
#define PROW(i, av) \
            fma2(acc2[i][0], av, b03.x); fma2(acc2[i][1], av, b03.y); \
            fma2(acc2[i][2], av, b47.x); fma2(acc2[i][3], av, b47.y);
            PROW(0, a01.x) PROW(1, a01.y)
            PROW(2, a23.x) PROW(3, a23.y)
            PROW(4, a45.x) PROW(5, a45.y)
            PROW(6, a67.x) PROW(7, a67.y)
#undef PROW
        }
    }
    // epilogue: write transposed [t][col][b] with bias.
    // thread owns rows m0 + ty*8 + i  ->  t = mblk*2 + (ty>>3), b = (ty&7)*8 + i
    int tt = mblk * 2 + (ty >> 3);
    int bb = (ty & 7) * 8;
#pragma unroll
    for (int q = 0; q < 4; q++) {
#pragma unroll
        for (int l = 0; l < 2; l++) {
            int col = n0 + tx * 8 + q * 2 + l;
            float bsv = g_bias[col];
            float v[8];
#pragma unroll
            for (int i = 0; i < 8; i++) {
                float2 u = unpack2(acc2[i][q]);
                v[i] = (l ? u.y : u.x) + bsv;
            }
            float* dst = &g_xprojT[((size_t)tt * NG + col) * BATCH + bb];
            *(float4*)dst       = make_float4(v[0], v[1], v[2], v[3]);
            *(float4*)(dst + 4) = make_float4(v[4], v[5], v[6], v[7]);
        }
    }
}

// ---------------- phase B: persistent LSTM recurrence (FFMA2) ----------------
// 128 CTAs: cta = (jt<<1) | b_half. Each CTA: 32 b x 16 jh x 4 gates (64 cols).
__global__ void __launch_bounds__(256) lstm_kernel() {
    __shared__ __align__(16) float Hs[32][32];   // h chunk  [kk][b]
    __shared__ __align__(16) float Wd[32][128];  // Wh chunk, (w,w)-duplicated pairs
    __shared__ __align__(16) float Gs[64][32];   // gate preacts [cc][b]
    __shared__ __align__(16) float cs[16][32];   // cell state [u][b] (persistent)

    int tid = threadIdx.x;
    int cta = blockIdx.x;
    int b0 = (cta & 1) * 32;
    int jt = cta >> 1;                 // jh base = jt*16
    int bg = tid & 7;                  // b group of 4
    int cg = tid >> 3;                 // col group of 2

    ((float*)cs)[tid] = 0.0f;
    ((float*)cs)[tid + 256] = 0.0f;

    int h_kk = tid >> 3, h_b4 = (tid & 7) * 4;
    const float2* wsrc = (const float2*)(g_whC + ((size_t)jt << 16)); // jt*1024*64 floats

    for (int t = 0; t < SEQ; t++) {
        const float* hc = g_h[t & 1];
        float* hn = g_h[(t + 1) & 1];

        ull acc00 = 0ULL, acc01 = 0ULL, acc10 = 0ULL, acc11 = 0ULL;

        for (int k0 = 0; k0 < HIDDEN; k0 += 32) {
            float4 hv = __ldcg((const float4*)&hc[(k0 + h_kk) * BATCH + b0 + h_b4]);
            const float2* wc = wsrc + k0 * 32;   // chunk = 32 k x 32 col-pairs
            float2 w0 = __ldg(&wc[tid]);
            float2 w1 = __ldg(&wc[tid + 256]);
            float2 w2 = __ldg(&wc[tid + 512]);
            float2 w3 = __ldg(&wc[tid + 768]);
            __syncthreads();
            *(float4*)&Hs[h_kk][h_b4] = hv;
            { int i = tid;       *(float4*)&Wd[i >> 5][(i & 31) * 4] = make_float4(w0.x, w0.x, w0.y, w0.y); }
            { int i = tid + 256; *(float4*)&Wd[i >> 5][(i & 31) * 4] = make_float4(w1.x, w1.x, w1.y, w1.y); }
            { int i = tid + 512; *(float4*)&Wd[i >> 5][(i & 31) * 4] = make_float4(w2.x, w2.x, w2.y, w2.y); }
            { int i = tid + 768; *(float4*)&Wd[i >> 5][(i & 31) * 4] = make_float4(w3.x, w3.x, w3.y, w3.y); }
            __syncthreads();
#pragma unroll
            for (int kk = 0; kk < 32; kk++) {
                ulonglong2 hp = *(const ulonglong2*)&Hs[kk][bg * 4];
                ulonglong2 wp = *(const ulonglong2*)&Wd[kk][cg * 4];
                fma2(acc00, hp.x, wp.x);
                fma2(acc10, hp.y, wp.x);
                fma2(acc01, hp.x, wp.y);
                fma2(acc11, hp.y, wp.y);
            }
        }

        // stage gate preacts: recurrent acc + precomputed x-proj (+bias)
#pragma unroll
        for (int j = 0; j < 2; j++) {
            int cc = cg * 2 + j;
            int gcol = (cc >> 4) * 1024 + jt * 16 + (cc & 15);
            float4 xv = __ldcg((const float4*)&g_xprojT[((size_t)t * NG + gcol) * BATCH + b0 + bg * 4]);
            float2 u0 = unpack2(j ? acc01 : acc00);
            float2 u1 = unpack2(j ? acc11 : acc10);
            Gs[cc][bg * 4 + 0] = u0.x + xv.x;
            Gs[cc][bg * 4 + 1] = u0.y + xv.y;
            Gs[cc][bg * 4 + 2] = u1.x + xv.z;
            Gs[cc][bg * 4 + 3] = u1.y + xv.w;
        }
        __syncthreads();

        // cell/hidden update: 2 cells per thread
#pragma unroll
        for (int e = 0; e < 2; e++) {
            int cell = tid + e * 256;
            int bb = cell & 31, u = cell >> 5;
            float f  = sigmoidf_(Gs[u][bb]);
            float ii = sigmoidf_(Gs[16 + u][bb]);
            float gg = tanhf(Gs[32 + u][bb]);
            float oo = sigmoidf_(Gs[48 + u][bb]);
            float c = cs[u][bb] * f + gg * ii;
            cs[u][bb] = c;
            hn[(jt * 16 + u) * BATCH + b0 + bb] = c * oo;   // no tanh (matches ref)
        }

        // grid-wide barrier among the 128 resident CTAs
        __threadfence();
        __syncthreads();
        if (tid == 0) {
            atomicAdd(&g_cnt[t], 1u);
            volatile unsigned* p = &g_cnt[t];
            while (*p < (unsigned)RCTAS) { }
        }
        __syncthreads();
    }
}

// ---------------- phase C: logits = h_final @ Wout + bout --------------------
__global__ void __launch_bounds__(256) gemmC_kernel(const float* __restrict__ Wout,
                                                    const float* __restrict__ bout,
                                                    float* __restrict__ out) {
    __shared__ __align__(16) float As[8][64];
    __shared__ __align__(16) float Bs[8][128];
    int tid = threadIdx.x;
    int n0 = blockIdx.x * 128;
    int ty = tid >> 4, tx = tid & 15;

    float acc[4][8];
#pragma unroll
    for (int i = 0; i < 4; i++)
#pragma unroll
        for (int j = 0; j < 8; j++) acc[i][j] = 0.0f;

    int akk = tid >> 5, am = (tid & 31) * 2;
    int bkk = tid >> 5, bn = (tid & 31) * 4;

    for (int k0 = 0; k0 < HIDDEN; k0 += 8) {
        float2 av = *(const float2*)&g_h[0][(k0 + akk) * BATCH + am];
        float4 bv = *(const float4*)(Wout + (size_t)(k0 + bkk) * VOCAB + n0 + bn);
        __syncthreads();
        *(float2*)&As[akk][am] = av;
        *(float4*)&Bs[bkk][bn] = bv;
        __syncthreads();
#pragma unroll
        for (int kk = 0; kk < 8; kk++) {
            float4 a = *(float4*)&As[kk][ty * 4];
            float4 b0 = *(float4*)&Bs[kk][tx * 8];
            float4 b1 = *(float4*)&Bs[kk][tx * 8 + 4];
            float aa[4] = {a.x, a.y, a.z, a.w};
            float bb[8] = {b0.x, b0.y, b0.z, b0.w, b1.x, b1.y, b1.z, b1.w};
#pragma unroll
            for (int i = 0; i < 4; i++)
#pragma unroll
                for (int j = 0; j < 8; j++)
                    acc[i][j] = fmaf(aa[i], bb[j], acc[i][j]);
        }
    }
#pragma unroll
    for (int i = 0; i < 4; i++) {
        int row = ty * 4 + i;
        size_t base = (size_t)row * VOCAB + n0 + tx * 8;
#pragma unroll
        for (int j = 0; j < 8; j++)
            out[base + j] = acc[i][j] + bout[n0 + tx * 8 + j];
    }
}

// ---------------- launcher ---------------------------------------------------
extern "C" void kernel_launch(void* const* d_in, const int* in_sizes, int n_in,
                              void* d_out, int out_size) {
    const int*   ids   = (const int*)d_in[0];
    const float* embed = (const float*)d_in[1];
    const float* Wf    = (const float*)d_in[2];
    const float* bf    = (const float*)d_in[3];
    const float* Wi    = (const float*)d_in[4];
    const float* bi    = (const float*)d_in[5];
    const float* Wc    = (const float*)d_in[6];
    const float* bc    = (const float*)d_in[7];
    const float* Wo    = (const float*)d_in[8];
    const float* bo    = (const float*)d_in[9];
    const float* Wout  = (const float*)d_in[10];
    const float* bout  = (const float*)d_in[11];

    prep_kernel<<<1024, 256>>>(ids, Wf, bf, Wi, bi, Wc, bc, Wo, bo);
    gemmA_kernel<<<dim3(NG / 128, M_A / 128), 256>>>(embed);
    lstm_kernel<<<RCTAS, 256>>>();
    gemmC_kernel<<<VOCAB / 128, 256>>>(Wout, bout, (float*)d_out);
}

// round 17
// speedup vs baseline: 1.2737x; 1.2711x over previous
#include <cuda_runtime.h>
#include <math.h>

#define VOCAB  32000
#define EMBED  512
#define HIDDEN 1024
#define BATCH  64
#define SEQ    512
#define NG     4096            // 4 * HIDDEN (f,i,g,o packed)
#define M_A    (SEQ * BATCH)   // 32768 rows for the input projection GEMM
#define RCTAS  128
#define JH_PER 8               // jh units per lstm CTA
#define CCOLS  32              // weight cols per lstm CTA (4 gates x 8 jh)
#define WSTR   1028            // W smem row stride (floats)
#define HSTR   36              // H smem row stride (floats)

// dynamic smem layout (floats)
#define SM_WS   0
#define SM_HS   (CCOLS * WSTR)                 // 32896
#define SM_GS   (SM_HS + 2 * BATCH * HSTR)     // + 4608
#define SM_CS   (SM_GS + CCOLS * BATCH)        // + 2048
#define SM_TOT  (SM_CS + JH_PER * BATCH)       // + 512 = 40064 floats
#define SMEM_BYTES (SM_TOT * 4)                // 160256 B

typedef unsigned long long ull;

// ---------------- device scratch (static: allocation-guard-safe) ------------
__device__ __align__(128) float g_xprojT[(size_t)SEQ * NG * BATCH]; // [t][col][b], bias added
__device__ __align__(128) float g_wxP[EMBED * NG];                  // Wx packed [k][col]
__device__ __align__(128) float g_whR[RCTAS * CCOLS * HIDDEN];      // Wh per-CTA [cta][c][k]
__device__ __align__(128) float g_bias[NG];
__device__ __align__(128) float g_h[2][BATCH * HIDDEN];             // h double buffer [b][jh]
__device__ __align__(128) int   g_idx[M_A];
__device__ unsigned g_cnt[SEQ];     // per-step grid barrier counters

__device__ __forceinline__ float sigmoidf_(float x) { return 1.0f / (1.0f + __expf(-x)); }

// packed fp32x2 FMA (Blackwell FFMA2): d.lo += a.lo*b.lo ; d.hi += a.hi*b.hi
__device__ __forceinline__ void fma2(ull& d, ull a, ull b) {
    asm("fma.rn.f32x2 %0, %1, %2, %0;" : "+l"(d) : "l"(a), "l"(b));
}
__device__ __forceinline__ float2 unpack2(ull v) {
    float2 f; asm("mov.b64 {%0,%1}, %2;" : "=f"(f.x), "=f"(f.y) : "l"(v)); return f;
}

// ---------------- prep: pack weights, gather indices, zero state -------------
__global__ void prep_kernel(const int* __restrict__ ids,
                            const float* __restrict__ Wf, const float* __restrict__ bf,
                            const float* __restrict__ Wi, const float* __restrict__ bi,
                            const float* __restrict__ Wc, const float* __restrict__ bc,
                            const float* __restrict__ Wo, const float* __restrict__ bo) {
    int tid = blockIdx.x * blockDim.x + threadIdx.x;
    int nt  = gridDim.x * blockDim.x;

    // Wh per-CTA: whR[cta][c][k] = W_g[(512+k)*1024 + cta*8 + jl], c = g*8+jl
    for (int i = tid; i < RCTAS * CCOLS * HIDDEN; i += nt) {
        int k = i & 1023, c = (i >> 10) & 31, cta = i >> 15;
        int g = c >> 3, jh = cta * 8 + (c & 7);
        const float* W = (g == 0) ? Wf : (g == 1) ? Wi : (g == 2) ? Wc : Wo;
        g_whR[i] = W[(EMBED + k) * HIDDEN + jh];
    }
    // Wx packed: wxP[k*4096 + col], col = g*1024 + jh
    for (int i = tid; i < EMBED * NG; i += nt) {
        int k = i >> 12, col = i & 4095;
        int g = col >> 10, jh = col & 1023;
        const float* W = (g == 0) ? Wf : (g == 1) ? Wi : (g == 2) ? Wc : Wo;
        g_wxP[i] = W[k * HIDDEN + jh];
    }
    for (int i = tid; i < NG; i += nt) {
        int g = i >> 10, jh = i & 1023;
        const float* b = (g == 0) ? bf : (g == 1) ? bi : (g == 2) ? bc : bo;
        g_bias[i] = b[jh];
    }
    for (int i = tid; i < M_A; i += nt)
        g_idx[i] = ids[(i & 63) * SEQ + (i >> 6)];   // row m = t*64+b -> ids[b*SEQ+t]
    for (int i = tid; i < BATCH * HIDDEN; i += nt)
        g_h[0][i] = 0.0f;
    for (int i = tid; i < SEQ; i += nt)
        g_cnt[i] = 0u;
}

// ---------------- phase A: xprojT = embed[ids] @ Wx + bias (FFMA2) -----------
// M=32768, N=4096, K=512. CTA tile 128x128, 256 thr, 8x8 per thread.
// Output layout transposed: [t][col][b].
__global__ void __launch_bounds__(256, 2) gemmA_kernel(const float* __restrict__ embed) {
    __shared__ __align__(16) float Ad[8][256];   // a duplicated (a,a) pairs
    __shared__ __align__(16) float Bs[8][128];
    int tid = threadIdx.x;
    int mblk = blockIdx.y, nblk = blockIdx.x;
    int m0 = mblk * 128, n0 = nblk * 128;
    int ty = tid >> 4, tx = tid & 15;

    ull acc2[8][4];
#pragma unroll
    for (int i = 0; i < 8; i++)
#pragma unroll
        for (int q = 0; q < 4; q++) acc2[i][q] = 0ULL;

    int am = tid >> 1, ak = (tid & 1) * 4;
    int arow = g_idx[m0 + am];
    const float* aptr = embed + (size_t)arow * EMBED + ak;
    int bk = tid >> 5, bn = (tid & 31) * 4;

    for (int k0 = 0; k0 < EMBED; k0 += 8) {
        float4 av = __ldg((const float4*)(aptr + k0));
        float4 bv = __ldg((const float4*)(g_wxP + (size_t)(k0 + bk) * NG + n0 + bn));
        __syncthreads();
        *(float2*)&Ad[ak + 0][2 * am] = make_float2(av.x, av.x);
        *(float2*)&Ad[ak + 1][2 * am] = make_float2(av.y, av.y);
        *(float2*)&Ad[ak + 2][2 * am] = make_float2(av.z, av.z);
        *(float2*)&Ad[ak + 3][2 * am] = make_float2(av.w, av.w);
        *(float4*)&Bs[bk][bn] = bv;
        __syncthreads();
#pragma unroll
        for (int kk = 0; kk < 8; kk++) {
            ulonglong2 a01 = *(const ulonglong2*)&Ad[kk][ty * 16 + 0];
            ulonglong2 a23 = *(const ulonglong2*)&Ad[kk][ty * 16 + 4];
            ulonglong2 a45 = *(const ulonglong2*)&Ad[kk][ty * 16 + 8];
            ulonglong2 a67 = *(const ulonglong2*)&Ad[kk][ty * 16 + 12];
            ulonglong2 b03 = *(const ulonglong2*)&Bs[kk][tx * 8];
            ulonglong2 b47 = *(const ulonglong2*)&Bs[kk][tx * 8 + 4];
#define PROW(i, av) \
            fma2(acc2[i][0], av, b03.x); fma2(acc2[i][1], av, b03.y); \
            fma2(acc2[i][2], av, b47.x); fma2(acc2[i][3], av, b47.y);
            PROW(0, a01.x) PROW(1, a01.y)
            PROW(2, a23.x) PROW(3, a23.y)
            PROW(4, a45.x) PROW(5, a45.y)
            PROW(6, a67.x) PROW(7, a67.y)
#undef PROW
        }
    }
    // epilogue: write transposed [t][col][b] with bias.
    int tt = mblk * 2 + (ty >> 3);
    int bb = (ty & 7) * 8;
#pragma unroll
    for (int q = 0; q < 4; q++) {
#pragma unroll
        for (int l = 0; l < 2; l++) {
            int col = n0 + tx * 8 + q * 2 + l;
            float bsv = g_bias[col];
            float v[8];
#pragma unroll
            for (int i = 0; i < 8; i++) {
                float2 u = unpack2(acc2[i][q]);
                v[i] = (l ? u.y : u.x) + bsv;
            }
            float* dst = &g_xprojT[((size_t)tt * NG + col) * BATCH + bb];
            *(float4*)dst       = make_float4(v[0], v[1], v[2], v[3]);
            *(float4*)(dst + 4) = make_float4(v[4], v[5], v[6], v[7]);
        }
    }
}

// ---------------- phase B: persistent LSTM, smem-resident W ------------------
// 128 CTAs, CTA owns jh in [cta*8, cta*8+8): 32 cols x 64 batch x K=1024.
// FFMA2 paired along K (even/odd lanes), folded at the end.
__global__ void __launch_bounds__(256) lstm_kernel() {
    extern __shared__ __align__(16) float sm[];
    float* Ws = sm + SM_WS;      // [32][1028]
    float* Hsm = sm + SM_HS;     // [2][64][36]
    float* Gs = sm + SM_GS;      // [32][64]
    float* cs = sm + SM_CS;      // [8][64]

    int tid = threadIdx.x;
    int cta = blockIdx.x;
    int jh0 = cta * JH_PER;

    // one-time W load into smem: 32768 floats
    const float4* wsrc = (const float4*)(g_whR + (size_t)cta * (CCOLS * HIDDEN));
#pragma unroll 4
    for (int i = tid; i < CCOLS * HIDDEN / 4; i += 256) {
        int c = i >> 8, k4 = i & 255;
        *(float4*)&Ws[c * WSTR + k4 * 4] = __ldg(&wsrc[i]);
    }
    cs[tid] = 0.0f;
    cs[tid + 256] = 0.0f;

    int lane = tid & 31, w = tid >> 5;
    int bg = (lane & 7) | ((w & 1) << 3);        // 0..15: b = bg + 16*i
    int cg = (lane >> 3) | ((w >> 1) << 2);      // 0..15: c = cg*2 + j

    // staging ids: thread loads h rows s_b and s_b+32, k-quad s_kq
    int s_kq = tid & 7;
    int s_b  = tid >> 3;

    // update ids: thread owns (jl = tid>>5, b = u_b2, u_b2+1)
    int u_jl = tid >> 5;
    int u_b2 = (lane) * 2;

    const float* wc0 = &Ws[(cg * 2) * WSTR];
    const float* wc1 = &Ws[(cg * 2 + 1) * WSTR];
    const float* hb0 = 0; // set per buffer

    __syncthreads();

    for (int t = 0; t < SEQ; t++) {
        const float* hc = g_h[t & 1];
        float* hn = g_h[(t + 1) & 1];

        // prologue: stage chunk 0 into buffer 0
        {
            float4 v0 = __ldcg((const float4*)&hc[s_b * HIDDEN + s_kq * 4]);
            float4 v1 = __ldcg((const float4*)&hc[(s_b + 32) * HIDDEN + s_kq * 4]);
            *(float4*)&Hsm[s_b * HSTR + s_kq * 4] = v0;
            *(float4*)&Hsm[(s_b + 32) * HSTR + s_kq * 4] = v1;
        }
        __syncthreads();

        ull acc[4][2];
#pragma unroll
        for (int i = 0; i < 4; i++) { acc[i][0] = 0ULL; acc[i][1] = 0ULL; }

        for (int ch = 0; ch < 32; ch++) {
            const float* H = Hsm + (ch & 1) * (BATCH * HSTR);
            float4 nv0, nv1;
            if (ch < 31) {
                nv0 = __ldcg((const float4*)&hc[s_b * HIDDEN + (ch + 1) * 32 + s_kq * 4]);
                nv1 = __ldcg((const float4*)&hc[(s_b + 32) * HIDDEN + (ch + 1) * 32 + s_kq * 4]);
            }
#pragma unroll
            for (int q = 0; q < 8; q++) {
                ulonglong2 h0 = *(const ulonglong2*)&H[(bg     ) * HSTR + q * 4];
                ulonglong2 h1 = *(const ulonglong2*)&H[(bg + 16) * HSTR + q * 4];
                ulonglong2 h2 = *(const ulonglong2*)&H[(bg + 32) * HSTR + q * 4];
                ulonglong2 h3 = *(const ulonglong2*)&H[(bg + 48) * HSTR + q * 4];
                ulonglong2 w0 = *(const ulonglong2*)&wc0[ch * 32 + q * 4];
                ulonglong2 w1 = *(const ulonglong2*)&wc1[ch * 32 + q * 4];
                fma2(acc[0][0], h0.x, w0.x); fma2(acc[0][0], h0.y, w0.y);
                fma2(acc[1][0], h1.x, w0.x); fma2(acc[1][0], h1.y, w0.y);
                fma2(acc[2][0], h2.x, w0.x); fma2(acc[2][0], h2.y, w0.y);
                fma2(acc[3][0], h3.x, w0.x); fma2(acc[3][0], h3.y, w0.y);
                fma2(acc[0][1], h0.x, w1.x); fma2(acc[0][1], h0.y, w1.y);
                fma2(acc[1][1], h1.x, w1.x); fma2(acc[1][1], h1.y, w1.y);
                fma2(acc[2][1], h2.x, w1.x); fma2(acc[2][1], h2.y, w1.y);
                fma2(acc[3][1], h3.x, w1.x); fma2(acc[3][1], h3.y, w1.y);
            }
            if (ch < 31) {
                float* Hn = Hsm + ((ch & 1) ^ 1) * (BATCH * HSTR);
                *(float4*)&Hn[s_b * HSTR + s_kq * 4] = nv0;
                *(float4*)&Hn[(s_b + 32) * HSTR + s_kq * 4] = nv1;
            }
            __syncthreads();
        }

        // fold even/odd K lanes, stage gate preacts
#pragma unroll
        for (int j = 0; j < 2; j++) {
            int c = cg * 2 + j;
#pragma unroll
            for (int i = 0; i < 4; i++) {
                float2 u = unpack2(acc[i][j]);
                Gs[c * BATCH + bg + 16 * i] = u.x + u.y;
            }
        }
        __syncthreads();

        // cell/hidden update: thread owns (jl, b2) and (jl, b2+1)
        {
            const float* xb = &g_xprojT[((size_t)t * NG + jh0 + u_jl) * BATCH + u_b2];
            float2 xf = __ldcs((const float2*)(xb));
            float2 xi = __ldcs((const float2*)(xb + (size_t)1024 * BATCH));
            float2 xg = __ldcs((const float2*)(xb + (size_t)2048 * BATCH));
            float2 xo = __ldcs((const float2*)(xb + (size_t)3072 * BATCH));
            float2 gf = *(const float2*)&Gs[(0 * 8 + u_jl) * BATCH + u_b2];
            float2 gi = *(const float2*)&Gs[(1 * 8 + u_jl) * BATCH + u_b2];
            float2 gg = *(const float2*)&Gs[(2 * 8 + u_jl) * BATCH + u_b2];
            float2 go = *(const float2*)&Gs[(3 * 8 + u_jl) * BATCH + u_b2];
            float2 cold = *(const float2*)&cs[u_jl * BATCH + u_b2];

            float f0 = sigmoidf_(gf.x + xf.x), f1 = sigmoidf_(gf.y + xf.y);
            float i0 = sigmoidf_(gi.x + xi.x), i1 = sigmoidf_(gi.y + xi.y);
            float g0 = tanhf(gg.x + xg.x),     g1 = tanhf(gg.y + xg.y);
            float o0 = sigmoidf_(go.x + xo.x), o1 = sigmoidf_(go.y + xo.y);
            float c0 = cold.x * f0 + g0 * i0;
            float c1 = cold.y * f1 + g1 * i1;
            *(float2*)&cs[u_jl * BATCH + u_b2] = make_float2(c0, c1);
            hn[(u_b2) * HIDDEN + jh0 + u_jl]     = c0 * o0;   // no tanh (matches ref)
            hn[(u_b2 + 1) * HIDDEN + jh0 + u_jl] = c1 * o1;
        }

        // grid-wide barrier among the 128 resident CTAs
        __threadfence();
        __syncthreads();
        if (tid == 0) {
            atomicAdd(&g_cnt[t], 1u);
            volatile unsigned* p = &g_cnt[t];
            while (*p < (unsigned)RCTAS) { }
        }
        __syncthreads();
    }
}

// ---------------- phase C: logits = h_final @ Wout + bout --------------------
__global__ void __launch_bounds__(256) gemmC_kernel(const float* __restrict__ Wout,
                                                    const float* __restrict__ bout,
                                                    float* __restrict__ out) {
    __shared__ __align__(16) float As[8][64];
    __shared__ __align__(16) float Bs[8][128];
    int tid = threadIdx.x;
    int n0 = blockIdx.x * 128;
    int ty = tid >> 4, tx = tid & 15;

    float acc[4][8];
#pragma unroll
    for (int i = 0; i < 4; i++)
#pragma unroll
        for (int j = 0; j < 8; j++) acc[i][j] = 0.0f;

    int akk = tid >> 5, am = (tid & 31) * 2;
    int bkk = tid >> 5, bn = (tid & 31) * 4;

    for (int k0 = 0; k0 < HIDDEN; k0 += 8) {
        // h layout is [b][jh]
        float a0 = g_h[0][(size_t)am * HIDDEN + k0 + akk];
        float a1 = g_h[0][(size_t)(am + 1) * HIDDEN + k0 + akk];
        float4 bv = *(const float4*)(Wout + (size_t)(k0 + bkk) * VOCAB + n0 + bn);
        __syncthreads();
        As[akk][am] = a0;
        As[akk][am + 1] = a1;
        *(float4*)&Bs[bkk][bn] = bv;
        __syncthreads();
#pragma unroll
        for (int kk = 0; kk < 8; kk++) {
            float4 a = *(float4*)&As[kk][ty * 4];
            float4 b0 = *(float4*)&Bs[kk][tx * 8];
            float4 b1 = *(float4*)&Bs[kk][tx * 8 + 4];
            float aa[4] = {a.x, a.y, a.z, a.w};
            float bb[8] = {b0.x, b0.y, b0.z, b0.w, b1.x, b1.y, b1.z, b1.w};
#pragma unroll
            for (int i = 0; i < 4; i++)
#pragma unroll
                for (int j = 0; j < 8; j++)
                    acc[i][j] = fmaf(aa[i], bb[j], acc[i][j]);
        }
    }
#pragma unroll
    for (int i = 0; i < 4; i++) {
        int row = ty * 4 + i;
        size_t base = (size_t)row * VOCAB + n0 + tx * 8;
#pragma unroll
        for (int j = 0; j < 8; j++)
            out[base + j] = acc[i][j] + bout[n0 + tx * 8 + j];
    }
}

// ---------------- launcher ---------------------------------------------------
extern "C" void kernel_launch(void* const* d_in, const int* in_sizes, int n_in,
                              void* d_out, int out_size) {
    const int*   ids   = (const int*)d_in[0];
    const float* embed = (const float*)d_in[1];
    const float* Wf    = (const float*)d_in[2];
    const float* bf    = (const float*)d_in[3];
    const float* Wi    = (const float*)d_in[4];
    const float* bi    = (const float*)d_in[5];
    const float* Wc    = (const float*)d_in[6];
    const float* bc    = (const float*)d_in[7];
    const float* Wo    = (const float*)d_in[8];
    const float* bo    = (const float*)d_in[9];
    const float* Wout  = (const float*)d_in[10];
    const float* bout  = (const float*)d_in[11];

    cudaFuncSetAttribute(lstm_kernel, cudaFuncAttributeMaxDynamicSharedMemorySize, SMEM_BYTES);

    prep_kernel<<<1024, 256>>>(ids, Wf, bf, Wi, bi, Wc, bc, Wo, bo);
    gemmA_kernel<<<dim3(NG / 128, M_A / 128), 256>>>(embed);
    lstm_kernel<<<RCTAS, 256, SMEM_BYTES>>>();
    gemmC_kernel<<<VOCAB / 128, 256>>>(Wout, bout, (float*)d_out);
}